// round 12
// baseline (speedup 1.0000x reference)
#include <cuda_runtime.h>
#include <cuda_fp16.h>
#include <cstdint>
#include <math.h>

#define BATCH 128
#define SEQ   512
#define INDIM 256
#define HID   1024
#define NCLS  10
#define PSTEP (4 * HID * BATCH)

// ---------------- device globals ----------------
__device__ float g_P[(size_t)SEQ * PSTEP];   // [s][q(4096)][b(128)]
__device__ __align__(16) __half g_xh[(size_t)BATCH * SEQ * INDIM];  // x fp16 [b][s][k]
__device__ __align__(16) __half g_Wihi[4096 * INDIM];   // W_ih hi fp16
__device__ __align__(16) __half g_Wilo[4096 * INDIM];   // W_ih lo fp16
__device__ __align__(16) __half g_h[2][HID * BATCH];    // [d][b] fp16 state (transposed!)
__device__ float g_hfin[BATCH * HID];                   // [b][d] final h
__device__ unsigned g_bar;
__device__ volatile unsigned g_flag;

__device__ __forceinline__ uint32_t smem_u32(const void* p) {
    uint32_t a;
    asm("{ .reg .u64 t; cvta.to.shared.u64 t, %1; cvt.u32.u64 %0, t; }" : "=r"(a) : "l"(p));
    return a;
}
__device__ __forceinline__ void cp16(uint32_t dst, const void* src) {
    asm volatile("cp.async.cg.shared.global [%0], [%1], 16;" :: "r"(dst), "l"(src));
}
#define CP_COMMIT() asm volatile("cp.async.commit_group;" ::: "memory")
#define CP_WAIT(n)  asm volatile("cp.async.wait_group %0;" :: "n"(n) : "memory")

__device__ __forceinline__ void ldm_x4(uint32_t &r0, uint32_t &r1, uint32_t &r2,
                                       uint32_t &r3, uint32_t addr) {
    asm volatile("ldmatrix.sync.aligned.m8n8.x4.shared.b16 {%0,%1,%2,%3}, [%4];"
        : "=r"(r0), "=r"(r1), "=r"(r2), "=r"(r3) : "r"(addr));
}
__device__ __forceinline__ void ldm_x4_t(uint32_t &r0, uint32_t &r1, uint32_t &r2,
                                         uint32_t &r3, uint32_t addr) {
    asm volatile("ldmatrix.sync.aligned.m8n8.x4.trans.shared.b16 {%0,%1,%2,%3}, [%4];"
        : "=r"(r0), "=r"(r1), "=r"(r2), "=r"(r3) : "r"(addr));
}
__device__ __forceinline__ void mma16816(float* c, uint32_t a0, uint32_t a1,
                                         uint32_t a2, uint32_t a3,
                                         uint32_t b0, uint32_t b1) {
    asm volatile(
        "mma.sync.aligned.m16n8k16.row.col.f32.f16.f16.f32 "
        "{%0,%1,%2,%3}, {%4,%5,%6,%7}, {%8,%9}, {%0,%1,%2,%3};"
        : "+f"(c[0]), "+f"(c[1]), "+f"(c[2]), "+f"(c[3])
        : "r"(a0), "r"(a1), "r"(a2), "r"(a3), "r"(b0), "r"(b1));
}
__device__ __forceinline__ float sigf(float x) { return 1.0f / (1.0f + __expf(-x)); }

// ---------------- pre-kernels ----------------
__global__ void init_state(const float* __restrict__ h0) {
    int idx = blockIdx.x * 256 + threadIdx.x;   // over [b][d]
    if (idx == 0) { g_bar = 0; g_flag = 0; }
    int b = idx >> 10, d = idx & 1023;
    g_h[0][d * BATCH + b] = __float2half(h0[idx]);
}
__global__ void cvt_x(const float* __restrict__ x) {
    size_t idx = (size_t)blockIdx.x * 256 + threadIdx.x;
    g_xh[idx] = __float2half(x[idx]);
}
__global__ void split_Wih(const float* __restrict__ W_ih) {
    int idx = blockIdx.x * 256 + threadIdx.x;
    float w = W_ih[idx];
    __half hi = __float2half(w);
    g_Wihi[idx] = hi;
    g_Wilo[idx] = __float2half(w - __half2float(hi));
}

// ---------------- xproj via mma.sync (fp16, W split 2-pass) ----------------
#define XP_PIT_A 264
#define XP_A_SZ  (64 * XP_PIT_A * 2)
#define XP_PIT_B 72
#define XP_B_SZ  (128 * XP_PIT_B * 2)
#define XP_SM_AHI 0
#define XP_SM_ALO XP_A_SZ
#define XP_SM_BIAS (2 * XP_A_SZ)
#define XP_SM_B   (XP_SM_BIAS + 256)
#define XP_SMEM   (XP_SM_B + 3 * XP_B_SZ)

__global__ __launch_bounds__(256, 1) void xproj_mma(
        const float* __restrict__ b_ih, const float* __restrict__ b_hh) {
    extern __shared__ char smem[];
    uint32_t sb = smem_u32(smem);
    int tid = threadIdx.x, lane = tid & 31, wid = tid >> 5;
    int li = lane >> 3, l7 = lane & 7;
    int qt = blockIdx.x, s = blockIdx.y;
    int qh = wid >> 2, bq = wid & 3;
    int q0 = qh * 32, b0 = bq * 32;

    float* bias = (float*)(smem + XP_SM_BIAS);
    if (tid < 64) {
        int q = qt * 64 + tid;
        bias[tid] = b_ih[q] + b_hh[q];
    }

    {
        #pragma unroll
        for (int i = 0; i < 8; ++i) {
            int idx = tid + i * 256;
            int row = idx >> 5, seg = idx & 31;
            cp16(sb + XP_SM_AHI + row * (XP_PIT_A * 2) + seg * 16,
                 g_Wihi + (size_t)(qt * 64 + row) * INDIM + seg * 8);
        }
        #pragma unroll
        for (int i = 0; i < 8; ++i) {
            int idx = tid + i * 256;
            int row = idx >> 5, seg = idx & 31;
            cp16(sb + XP_SM_ALO + row * (XP_PIT_A * 2) + seg * 16,
                 g_Wilo + (size_t)(qt * 64 + row) * INDIM + seg * 8);
        }
    }
    int brow[4], bseg[4];
    #pragma unroll
    for (int i = 0; i < 4; ++i) { int u = tid + i * 256; brow[i] = u >> 3; bseg[i] = u & 7; }

    auto issueB = [&](int c, int st) {
        uint32_t dst = sb + XP_SM_B + st * XP_B_SZ;
        #pragma unroll
        for (int i = 0; i < 4; ++i)
            cp16(dst + brow[i] * (XP_PIT_B * 2) + bseg[i] * 16,
                 g_xh + (size_t)brow[i] * (SEQ * INDIM) + (size_t)s * INDIM + c * 64 + bseg[i] * 8);
        CP_COMMIT();
    };
    issueB(0, 0);
    issueB(1, 1);

    uint32_t aOff[2];
    #pragma unroll
    for (int mt = 0; mt < 2; ++mt) {
        int row = q0 + mt * 16 + (li & 1) * 8 + l7;
        aOff[mt] = sb + XP_SM_AHI + (uint32_t)row * (XP_PIT_A * 2) + (li >> 1) * 16;
    }
    uint32_t bOff[2];
    #pragma unroll
    for (int p = 0; p < 2; ++p) {
        int row = b0 + p * 16 + (li >> 1) * 8 + l7;
        bOff[p] = (uint32_t)row * (XP_PIT_B * 2) + (li & 1) * 16;
    }

    float acc[2][4][4];
    #pragma unroll
    for (int mt = 0; mt < 2; ++mt)
        #pragma unroll
        for (int n = 0; n < 4; ++n)
            #pragma unroll
            for (int e = 0; e < 4; ++e) acc[mt][n][e] = 0.0f;

    #pragma unroll 1
    for (int c = 0; c < 4; ++c) {
        if (c == 3) { CP_WAIT(0); } else { CP_WAIT(1); }
        __syncthreads();
        if (c + 2 < 4) issueB(c + 2, (c + 2) % 3);
        uint32_t stBase = sb + XP_SM_B + (c % 3) * XP_B_SZ;
        uint32_t kByte = (uint32_t)c * 128;
        #pragma unroll
        for (int ks = 0; ks < 4; ++ks) {
            uint32_t bfr[4][2];
            #pragma unroll
            for (int p = 0; p < 2; ++p)
                ldm_x4(bfr[2*p][0], bfr[2*p][1], bfr[2*p+1][0], bfr[2*p+1][1],
                       stBase + bOff[p] + ks * 32);
            #pragma unroll
            for (int mt = 0; mt < 2; ++mt) {
                uint32_t a0, a1, a2, a3;
                ldm_x4(a0, a1, a2, a3, aOff[mt] + kByte + ks * 32);
                #pragma unroll
                for (int n = 0; n < 4; ++n)
                    mma16816(acc[mt][n], a0, a1, a2, a3, bfr[n][0], bfr[n][1]);
            }
            #pragma unroll
            for (int mt = 0; mt < 2; ++mt) {
                uint32_t a0, a1, a2, a3;
                ldm_x4(a0, a1, a2, a3, aOff[mt] + (uint32_t)XP_A_SZ + kByte + ks * 32);
                #pragma unroll
                for (int n = 0; n < 4; ++n)
                    mma16816(acc[mt][n], a0, a1, a2, a3, bfr[n][0], bfr[n][1]);
            }
        }
        __syncthreads();
    }

    size_t sbase = (size_t)s * PSTEP;
    #pragma unroll
    for (int mt = 0; mt < 2; ++mt) {
        #pragma unroll
        for (int n = 0; n < 4; ++n) {
            int rl0 = q0 + mt * 16 + (lane >> 2);
            int col = b0 + n * 8 + (lane & 3) * 2;
            int q0g = qt * 64 + rl0;
            float bv0 = bias[rl0], bv1 = bias[rl0 + 8];
            *(float2*)&g_P[sbase + (size_t)q0g * BATCH + col] =
                make_float2(acc[mt][n][0] + bv0, acc[mt][n][1] + bv0);
            *(float2*)&g_P[sbase + (size_t)(q0g + 8) * BATCH + col] =
                make_float2(acc[mt][n][2] + bv1, acc[mt][n][3] + bv1);
        }
    }
}

// ---------------- persistent LSTM recurrence, fp16 single-pass, [d][b] state ----------------
#define PIT_A 1032
#define SM_A  0
#define SM_P  66048
#define SM_B  82432
#define SLICE_PITCH 48           /* bytes per k-row: 16 batches fp16 (32B) + 16 pad */
#define SLICE_STRIDE 3072        /* 64 k-rows x 48 B */
#define NSTG 4
#define STEP_SMEM (SM_B + 8 * NSTG * SLICE_STRIDE)   /* 180736 */

__global__ __launch_bounds__(256, 1) void step_persist(
        const float* __restrict__ W_hh, const float* __restrict__ c0) {
    extern __shared__ char smem[];
    uint32_t sb = smem_u32(smem);
    int tid = threadIdx.x, lane = tid & 31, wid = tid >> 5;
    int li = lane >> 3, l7 = lane & 7;
    int jd = lane >> 2, tc = lane & 3;
    int ct = blockIdx.x;

    __half* sA = (__half*)(smem + SM_A);   // [32][1032]
    float* Psm = (float*)(smem + SM_P);    // [32][128]

    // ---- load A once (fp16 single) ----
    {
        int lr = tid >> 3, seg = tid & 7;
        int gate = lr >> 3, jj = lr & 7;
        const float* src = W_hh + (size_t)(gate * HID + ct * 8 + jj) * HID + seg * 128;
        #pragma unroll 4
        for (int i = 0; i < 32; ++i) {
            float4 v = *(const float4*)(src + i * 4);
            int k = seg * 128 + i * 4;
            sA[lr * PIT_A + k + 0] = __float2half(v.x);
            sA[lr * PIT_A + k + 1] = __float2half(v.y);
            sA[lr * PIT_A + k + 2] = __float2half(v.z);
            sA[lr * PIT_A + k + 3] = __float2half(v.w);
        }
    }

    // ---- c-state in registers ----
    float creg[2][2];
    {
        int d = ct * 8 + jd;
        #pragma unroll
        for (int n = 0; n < 2; ++n)
            #pragma unroll
            for (int e = 0; e < 2; ++e)
                creg[n][e] = c0[(size_t)(wid * 16 + n * 8 + 2 * tc + e) * HID + d];
    }

    uint32_t aOff[2];
    #pragma unroll
    for (int mt = 0; mt < 2; ++mt) {
        int row = mt * 16 + (li & 1) * 8 + l7;
        aOff[mt] = sb + SM_A + (uint32_t)row * (PIT_A * 2) + (li >> 1) * 16;
    }
    // B (trans): tile li: k-rows (li&1)*8 + l7, batch-halves (li>>1)*16 bytes
    uint32_t bOff = (uint32_t)((li & 1) * 8 + l7) * SLICE_PITCH + (li >> 1) * 16;
    // B cp coords: 4 units/thread, unit u = lane + i*32: k-row = u>>1, half = u&1
    int bkr[4], bhf[4];
    #pragma unroll
    for (int i = 0; i < 4; ++i) { int u = lane + i * 32; bkr[i] = u >> 1; bhf[i] = u & 1; }
    int pq[4], ps[4];
    #pragma unroll
    for (int i = 0; i < 4; ++i) { int u = tid + i * 256; pq[i] = u >> 5; ps[i] = u & 31; }

    uint32_t myStage0 = sb + SM_B + (uint32_t)wid * NSTG * SLICE_STRIDE;

    __syncthreads();

    // prefetch P(0)
    {
        #pragma unroll
        for (int i = 0; i < 4; ++i) {
            int qg = (pq[i] >> 3) * HID + ct * 8 + (pq[i] & 7);
            cp16(sb + SM_P + pq[i] * 512 + ps[i] * 16, g_P + (size_t)qg * BATCH + ps[i] * 4);
        }
        CP_COMMIT();
    }

    #pragma unroll 1
    for (int s = 0; s < SEQ; ++s) {
        const __half* h_in = g_h[s & 1];        // [d][b]
        __half* h_out = g_h[(s + 1) & 1];

        // issue B chunks 0..2
        #pragma unroll
        for (int cc = 0; cc < 3; ++cc) {
            uint32_t dst = myStage0 + cc * SLICE_STRIDE;
            #pragma unroll
            for (int i = 0; i < 4; ++i)
                cp16(dst + bkr[i] * SLICE_PITCH + bhf[i] * 16,
                     h_in + (size_t)(cc * 64 + bkr[i]) * BATCH + wid * 16 + bhf[i] * 8);
            CP_COMMIT();
        }

        float acc[2][2][4];
        #pragma unroll
        for (int mt = 0; mt < 2; ++mt)
            #pragma unroll
            for (int n = 0; n < 2; ++n)
                #pragma unroll
                for (int e = 0; e < 4; ++e) acc[mt][n][e] = 0.0f;

        #pragma unroll 1
        for (int c = 0; c < 16; ++c) {
            if (c <= 13) { CP_WAIT(2); } else if (c == 14) { CP_WAIT(1); } else { CP_WAIT(0); }
            __syncwarp();
            if (c + 3 < 16) {
                int cn = c + 3;
                uint32_t dst = myStage0 + (cn & (NSTG - 1)) * SLICE_STRIDE;
                #pragma unroll
                for (int i = 0; i < 4; ++i)
                    cp16(dst + bkr[i] * SLICE_PITCH + bhf[i] * 16,
                         h_in + (size_t)(cn * 64 + bkr[i]) * BATCH + wid * 16 + bhf[i] * 8);
                CP_COMMIT();
            }
            uint32_t stBase = myStage0 + (c & (NSTG - 1)) * SLICE_STRIDE;
            uint32_t kByte = (uint32_t)c * 128;
            #pragma unroll
            for (int ks = 0; ks < 4; ++ks) {
                uint32_t b0, b1, b2, b3;
                ldm_x4_t(b0, b1, b2, b3, stBase + bOff + ks * (16 * SLICE_PITCH));
                #pragma unroll
                for (int mt = 0; mt < 2; ++mt) {
                    uint32_t a0, a1, a2, a3;
                    ldm_x4(a0, a1, a2, a3, aOff[mt] + kByte + ks * 32);
                    mma16816(acc[mt][0], a0, a1, a2, a3, b0, b1);
                    mma16816(acc[mt][1], a0, a1, a2, a3, b2, b3);
                }
            }
        }

        // ---- LSTM cell in-register; coalesced [d][b] half2 stores ----
        {
            int d = ct * 8 + jd;
            bool last = (s == SEQ - 1);
            #pragma unroll
            for (int n = 0; n < 2; ++n) {
                int col = wid * 16 + n * 8 + 2 * tc;
                float2 pi = *(const float2*)&Psm[(0 * 8 + jd) * 128 + col];
                float2 pf = *(const float2*)&Psm[(1 * 8 + jd) * 128 + col];
                float2 pg = *(const float2*)&Psm[(2 * 8 + jd) * 128 + col];
                float2 po = *(const float2*)&Psm[(3 * 8 + jd) * 128 + col];
                float hv[2];
                #pragma unroll
                for (int e = 0; e < 2; ++e) {
                    float zi = acc[0][n][e]     + (e ? pi.y : pi.x);
                    float zf = acc[0][n][2 + e] + (e ? pf.y : pf.x);
                    float zg = acc[1][n][e]     + (e ? pg.y : pg.x);
                    float zo = acc[1][n][2 + e] + (e ? po.y : po.x);
                    float iv = sigf(zi), fv = sigf(zf), gv = tanhf(zg), ov = sigf(zo);
                    creg[n][e] = fv * creg[n][e] + iv * gv;
                    hv[e] = ov * tanhf(creg[n][e]);
                }
                __half2 hp; hp.x = __float2half(hv[0]); hp.y = __float2half(hv[1]);
                *(__half2*)&h_out[(size_t)d * BATCH + col] = hp;
                if (last) {
                    g_hfin[(size_t)col * HID + d]       = hv[0];
                    g_hfin[(size_t)(col + 1) * HID + d] = hv[1];
                }
            }
        }

        // ---- arrive / overlap P prefetch / wait ----
        __threadfence();
        __syncthreads();
        unsigned target = (unsigned)(s + 1);
        if (tid == 0) {
            unsigned old = atomicAdd(&g_bar, 1u);
            if (old == 128u * target - 1u) g_flag = target;
        }
        if (s + 1 < SEQ) {
            const float* Pg = g_P + (size_t)(s + 1) * PSTEP;
            #pragma unroll
            for (int i = 0; i < 4; ++i) {
                int qg = (pq[i] >> 3) * HID + ct * 8 + (pq[i] & 7);
                cp16(sb + SM_P + pq[i] * 512 + ps[i] * 16, Pg + (size_t)qg * BATCH + ps[i] * 4);
            }
            CP_COMMIT();
        }
        if (tid == 0) {
            while (g_flag < target) { }
            __threadfence();
        }
        __syncthreads();
    }
}

// ---------------- classifier ----------------
__global__ void out_kernel(const float* __restrict__ W_out,
                           const float* __restrict__ b_out,
                           float* __restrict__ out) {
    int c = blockIdx.x, b = blockIdx.y;
    const float* h = g_hfin + (size_t)b * HID;
    float sum = 0.0f;
    for (int d = threadIdx.x; d < HID; d += 128)
        sum += h[d] * W_out[c * HID + d];
    #pragma unroll
    for (int o = 16; o; o >>= 1) sum += __shfl_xor_sync(0xFFFFFFFFu, sum, o);
    __shared__ float red[4];
    if ((threadIdx.x & 31) == 0) red[threadIdx.x >> 5] = sum;
    __syncthreads();
    if (threadIdx.x == 0)
        out[b * NCLS + c] = red[0] + red[1] + red[2] + red[3] + b_out[c];
}

extern "C" void kernel_launch(void* const* d_in, const int* in_sizes, int n_in,
                              void* d_out, int out_size) {
    const float* x     = (const float*)d_in[0];
    const float* h0    = (const float*)d_in[1];
    const float* c0    = (const float*)d_in[2];
    const float* W_ih  = (const float*)d_in[3];
    const float* W_hh  = (const float*)d_in[4];
    const float* b_ih  = (const float*)d_in[5];
    const float* b_hh  = (const float*)d_in[6];
    const float* W_out = (const float*)d_in[7];
    const float* b_out = (const float*)d_in[8];
    float* out = (float*)d_out;

    cudaFuncSetAttribute(xproj_mma, cudaFuncAttributeMaxDynamicSharedMemorySize, XP_SMEM);
    cudaFuncSetAttribute(step_persist, cudaFuncAttributeMaxDynamicSharedMemorySize, STEP_SMEM);

    init_state<<<BATCH * HID / 256, 256>>>(h0);
    cvt_x<<<BATCH * SEQ * INDIM / 256, 256>>>(x);
    split_Wih<<<4096 * INDIM / 256, 256>>>(W_ih);
    xproj_mma<<<dim3(64, SEQ), 256, XP_SMEM>>>(b_ih, b_hh);
    step_persist<<<128, 256, STEP_SMEM>>>(W_hh, c0);
    out_kernel<<<dim3(NCLS, BATCH), 128>>>(W_out, b_out, out);
}

// round 13
// speedup vs baseline: 1.0225x; 1.0225x over previous
#include <cuda_runtime.h>
#include <cuda_fp16.h>
#include <cstdint>
#include <math.h>

#define BATCH 128
#define SEQ   512
#define INDIM 256
#define HID   1024
#define NCLS  10
#define PSTEP (4 * HID * BATCH)

// ---------------- device globals ----------------
__device__ float g_P[(size_t)SEQ * PSTEP];   // [s][q(4096)][b(128)]
__device__ __align__(16) __half g_xh[(size_t)BATCH * SEQ * INDIM];  // x fp16 [b][s][k]
__device__ __align__(16) __half g_Wihi[4096 * INDIM];   // W_ih hi fp16
__device__ __align__(16) __half g_Wilo[4096 * INDIM];   // W_ih lo fp16
__device__ __align__(16) __half g_h[2][HID * BATCH];    // [d][b] fp16 state (transposed!)
__device__ float g_hfin[BATCH * HID];                   // [b][d] final h
__device__ unsigned g_bar;
__device__ volatile unsigned g_flag;

__device__ __forceinline__ uint32_t smem_u32(const void* p) {
    uint32_t a;
    asm("{ .reg .u64 t; cvta.to.shared.u64 t, %1; cvt.u32.u64 %0, t; }" : "=r"(a) : "l"(p));
    return a;
}
__device__ __forceinline__ void cp16(uint32_t dst, const void* src) {
    asm volatile("cp.async.cg.shared.global [%0], [%1], 16;" :: "r"(dst), "l"(src));
}
#define CP_COMMIT() asm volatile("cp.async.commit_group;" ::: "memory")
#define CP_WAIT(n)  asm volatile("cp.async.wait_group %0;" :: "n"(n) : "memory")

__device__ __forceinline__ void ldm_x4(uint32_t &r0, uint32_t &r1, uint32_t &r2,
                                       uint32_t &r3, uint32_t addr) {
    asm volatile("ldmatrix.sync.aligned.m8n8.x4.shared.b16 {%0,%1,%2,%3}, [%4];"
        : "=r"(r0), "=r"(r1), "=r"(r2), "=r"(r3) : "r"(addr));
}
__device__ __forceinline__ void ldm_x4_t(uint32_t &r0, uint32_t &r1, uint32_t &r2,
                                         uint32_t &r3, uint32_t addr) {
    asm volatile("ldmatrix.sync.aligned.m8n8.x4.trans.shared.b16 {%0,%1,%2,%3}, [%4];"
        : "=r"(r0), "=r"(r1), "=r"(r2), "=r"(r3) : "r"(addr));
}
__device__ __forceinline__ void mma16816(float* c, uint32_t a0, uint32_t a1,
                                         uint32_t a2, uint32_t a3,
                                         uint32_t b0, uint32_t b1) {
    asm volatile(
        "mma.sync.aligned.m16n8k16.row.col.f32.f16.f16.f32 "
        "{%0,%1,%2,%3}, {%4,%5,%6,%7}, {%8,%9}, {%0,%1,%2,%3};"
        : "+f"(c[0]), "+f"(c[1]), "+f"(c[2]), "+f"(c[3])
        : "r"(a0), "r"(a1), "r"(a2), "r"(a3), "r"(b0), "r"(b1));
}
__device__ __forceinline__ float sigf(float x) { return 1.0f / (1.0f + __expf(-x)); }

// ---------------- pre-kernels ----------------
__global__ void init_state(const float* __restrict__ h0) {
    int idx = blockIdx.x * 256 + threadIdx.x;   // over [b][d]
    if (idx == 0) { g_bar = 0; g_flag = 0; }
    int b = idx >> 10, d = idx & 1023;
    g_h[0][d * BATCH + b] = __float2half(h0[idx]);
}
__global__ void cvt_x(const float* __restrict__ x) {
    size_t idx = (size_t)blockIdx.x * 256 + threadIdx.x;
    g_xh[idx] = __float2half(x[idx]);
}
__global__ void split_Wih(const float* __restrict__ W_ih) {
    int idx = blockIdx.x * 256 + threadIdx.x;
    float w = W_ih[idx];
    __half hi = __float2half(w);
    g_Wihi[idx] = hi;
    g_Wilo[idx] = __float2half(w - __half2float(hi));
}

// ---------------- xproj via mma.sync (fp16, W split 2-pass) ----------------
#define XP_PIT_A 264
#define XP_A_SZ  (64 * XP_PIT_A * 2)
#define XP_PIT_B 72
#define XP_B_SZ  (128 * XP_PIT_B * 2)
#define XP_SM_AHI 0
#define XP_SM_ALO XP_A_SZ
#define XP_SM_BIAS (2 * XP_A_SZ)
#define XP_SM_B   (XP_SM_BIAS + 256)
#define XP_SMEM   (XP_SM_B + 3 * XP_B_SZ)

__global__ __launch_bounds__(256, 1) void xproj_mma(
        const float* __restrict__ b_ih, const float* __restrict__ b_hh) {
    extern __shared__ char smem[];
    uint32_t sb = smem_u32(smem);
    int tid = threadIdx.x, lane = tid & 31, wid = tid >> 5;
    int li = lane >> 3, l7 = lane & 7;
    int qt = blockIdx.x, s = blockIdx.y;
    int qh = wid >> 2, bq = wid & 3;
    int q0 = qh * 32, b0 = bq * 32;

    float* bias = (float*)(smem + XP_SM_BIAS);
    if (tid < 64) {
        int q = qt * 64 + tid;
        bias[tid] = b_ih[q] + b_hh[q];
    }

    {
        #pragma unroll
        for (int i = 0; i < 8; ++i) {
            int idx = tid + i * 256;
            int row = idx >> 5, seg = idx & 31;
            cp16(sb + XP_SM_AHI + row * (XP_PIT_A * 2) + seg * 16,
                 g_Wihi + (size_t)(qt * 64 + row) * INDIM + seg * 8);
        }
        #pragma unroll
        for (int i = 0; i < 8; ++i) {
            int idx = tid + i * 256;
            int row = idx >> 5, seg = idx & 31;
            cp16(sb + XP_SM_ALO + row * (XP_PIT_A * 2) + seg * 16,
                 g_Wilo + (size_t)(qt * 64 + row) * INDIM + seg * 8);
        }
    }
    int brow[4], bseg[4];
    #pragma unroll
    for (int i = 0; i < 4; ++i) { int u = tid + i * 256; brow[i] = u >> 3; bseg[i] = u & 7; }

    auto issueB = [&](int c, int st) {
        uint32_t dst = sb + XP_SM_B + st * XP_B_SZ;
        #pragma unroll
        for (int i = 0; i < 4; ++i)
            cp16(dst + brow[i] * (XP_PIT_B * 2) + bseg[i] * 16,
                 g_xh + (size_t)brow[i] * (SEQ * INDIM) + (size_t)s * INDIM + c * 64 + bseg[i] * 8);
        CP_COMMIT();
    };
    issueB(0, 0);
    issueB(1, 1);

    uint32_t aOff[2];
    #pragma unroll
    for (int mt = 0; mt < 2; ++mt) {
        int row = q0 + mt * 16 + (li & 1) * 8 + l7;
        aOff[mt] = sb + XP_SM_AHI + (uint32_t)row * (XP_PIT_A * 2) + (li >> 1) * 16;
    }
    uint32_t bOff[2];
    #pragma unroll
    for (int p = 0; p < 2; ++p) {
        int row = b0 + p * 16 + (li >> 1) * 8 + l7;
        bOff[p] = (uint32_t)row * (XP_PIT_B * 2) + (li & 1) * 16;
    }

    float acc[2][4][4];
    #pragma unroll
    for (int mt = 0; mt < 2; ++mt)
        #pragma unroll
        for (int n = 0; n < 4; ++n)
            #pragma unroll
            for (int e = 0; e < 4; ++e) acc[mt][n][e] = 0.0f;

    #pragma unroll 1
    for (int c = 0; c < 4; ++c) {
        if (c == 3) { CP_WAIT(0); } else { CP_WAIT(1); }
        __syncthreads();
        if (c + 2 < 4) issueB(c + 2, (c + 2) % 3);
        uint32_t stBase = sb + XP_SM_B + (c % 3) * XP_B_SZ;
        uint32_t kByte = (uint32_t)c * 128;
        #pragma unroll
        for (int ks = 0; ks < 4; ++ks) {
            uint32_t bfr[4][2];
            #pragma unroll
            for (int p = 0; p < 2; ++p)
                ldm_x4(bfr[2*p][0], bfr[2*p][1], bfr[2*p+1][0], bfr[2*p+1][1],
                       stBase + bOff[p] + ks * 32);
            #pragma unroll
            for (int mt = 0; mt < 2; ++mt) {
                uint32_t a0, a1, a2, a3;
                ldm_x4(a0, a1, a2, a3, aOff[mt] + kByte + ks * 32);
                #pragma unroll
                for (int n = 0; n < 4; ++n)
                    mma16816(acc[mt][n], a0, a1, a2, a3, bfr[n][0], bfr[n][1]);
            }
            #pragma unroll
            for (int mt = 0; mt < 2; ++mt) {
                uint32_t a0, a1, a2, a3;
                ldm_x4(a0, a1, a2, a3, aOff[mt] + (uint32_t)XP_A_SZ + kByte + ks * 32);
                #pragma unroll
                for (int n = 0; n < 4; ++n)
                    mma16816(acc[mt][n], a0, a1, a2, a3, bfr[n][0], bfr[n][1]);
            }
        }
        __syncthreads();
    }

    size_t sbase = (size_t)s * PSTEP;
    #pragma unroll
    for (int mt = 0; mt < 2; ++mt) {
        #pragma unroll
        for (int n = 0; n < 4; ++n) {
            int rl0 = q0 + mt * 16 + (lane >> 2);
            int col = b0 + n * 8 + (lane & 3) * 2;
            int q0g = qt * 64 + rl0;
            float bv0 = bias[rl0], bv1 = bias[rl0 + 8];
            *(float2*)&g_P[sbase + (size_t)q0g * BATCH + col] =
                make_float2(acc[mt][n][0] + bv0, acc[mt][n][1] + bv0);
            *(float2*)&g_P[sbase + (size_t)(q0g + 8) * BATCH + col] =
                make_float2(acc[mt][n][2] + bv1, acc[mt][n][3] + bv1);
        }
    }
}

// ---------------- persistent LSTM recurrence, fp16 single-pass, [d][b] state ----------------
#define PIT_A 1032
#define SM_A  0
#define SM_P  66048
#define SM_B  82432
#define SLICE_PITCH 48           /* bytes per k-row: 16 batches fp16 (32B) + 16 pad */
#define SLICE_STRIDE 3072        /* 64 k-rows x 48 B */
#define NSTG 4
#define STEP_SMEM (SM_B + 8 * NSTG * SLICE_STRIDE)   /* 180736 */

__global__ __launch_bounds__(256, 1) void step_persist(
        const float* __restrict__ W_hh, const float* __restrict__ c0) {
    extern __shared__ char smem[];
    uint32_t sb = smem_u32(smem);
    int tid = threadIdx.x, lane = tid & 31, wid = tid >> 5;
    int li = lane >> 3, l7 = lane & 7;
    int jd = lane >> 2, tc = lane & 3;
    int ct = blockIdx.x;

    __half* sA = (__half*)(smem + SM_A);   // [32][1032]
    float* Psm = (float*)(smem + SM_P);    // [32][128]

    // ---- load A once (fp16 single) ----
    {
        int lr = tid >> 3, seg = tid & 7;
        int gate = lr >> 3, jj = lr & 7;
        const float* src = W_hh + (size_t)(gate * HID + ct * 8 + jj) * HID + seg * 128;
        #pragma unroll 4
        for (int i = 0; i < 32; ++i) {
            float4 v = *(const float4*)(src + i * 4);
            int k = seg * 128 + i * 4;
            sA[lr * PIT_A + k + 0] = __float2half(v.x);
            sA[lr * PIT_A + k + 1] = __float2half(v.y);
            sA[lr * PIT_A + k + 2] = __float2half(v.z);
            sA[lr * PIT_A + k + 3] = __float2half(v.w);
        }
    }

    // ---- c-state in registers ----
    float creg[2][2];
    {
        int d = ct * 8 + jd;
        #pragma unroll
        for (int n = 0; n < 2; ++n)
            #pragma unroll
            for (int e = 0; e < 2; ++e)
                creg[n][e] = c0[(size_t)(wid * 16 + n * 8 + 2 * tc + e) * HID + d];
    }

    uint32_t aOff[2];
    #pragma unroll
    for (int mt = 0; mt < 2; ++mt) {
        int row = mt * 16 + (li & 1) * 8 + l7;
        aOff[mt] = sb + SM_A + (uint32_t)row * (PIT_A * 2) + (li >> 1) * 16;
    }
    // B (trans): tile li: k-rows (li&1)*8 + l7, batch-halves (li>>1)*16 bytes
    uint32_t bOff = (uint32_t)((li & 1) * 8 + l7) * SLICE_PITCH + (li >> 1) * 16;
    // B cp coords: 4 units/thread, unit u = lane + i*32: k-row = u>>1, half = u&1
    int bkr[4], bhf[4];
    #pragma unroll
    for (int i = 0; i < 4; ++i) { int u = lane + i * 32; bkr[i] = u >> 1; bhf[i] = u & 1; }
    int pq[4], ps[4];
    #pragma unroll
    for (int i = 0; i < 4; ++i) { int u = tid + i * 256; pq[i] = u >> 5; ps[i] = u & 31; }

    uint32_t myStage0 = sb + SM_B + (uint32_t)wid * NSTG * SLICE_STRIDE;

    __syncthreads();

    // prefetch P(0)
    {
        #pragma unroll
        for (int i = 0; i < 4; ++i) {
            int qg = (pq[i] >> 3) * HID + ct * 8 + (pq[i] & 7);
            cp16(sb + SM_P + pq[i] * 512 + ps[i] * 16, g_P + (size_t)qg * BATCH + ps[i] * 4);
        }
        CP_COMMIT();
    }

    #pragma unroll 1
    for (int s = 0; s < SEQ; ++s) {
        const __half* h_in = g_h[s & 1];        // [d][b]
        __half* h_out = g_h[(s + 1) & 1];

        // issue B chunks 0..2
        #pragma unroll
        for (int cc = 0; cc < 3; ++cc) {
            uint32_t dst = myStage0 + cc * SLICE_STRIDE;
            #pragma unroll
            for (int i = 0; i < 4; ++i)
                cp16(dst + bkr[i] * SLICE_PITCH + bhf[i] * 16,
                     h_in + (size_t)(cc * 64 + bkr[i]) * BATCH + wid * 16 + bhf[i] * 8);
            CP_COMMIT();
        }

        float acc[2][2][4];
        #pragma unroll
        for (int mt = 0; mt < 2; ++mt)
            #pragma unroll
            for (int n = 0; n < 2; ++n)
                #pragma unroll
                for (int e = 0; e < 4; ++e) acc[mt][n][e] = 0.0f;

        #pragma unroll 1
        for (int c = 0; c < 16; ++c) {
            if (c <= 13) { CP_WAIT(2); } else if (c == 14) { CP_WAIT(1); } else { CP_WAIT(0); }
            __syncwarp();
            if (c + 3 < 16) {
                int cn = c + 3;
                uint32_t dst = myStage0 + (cn & (NSTG - 1)) * SLICE_STRIDE;
                #pragma unroll
                for (int i = 0; i < 4; ++i)
                    cp16(dst + bkr[i] * SLICE_PITCH + bhf[i] * 16,
                         h_in + (size_t)(cn * 64 + bkr[i]) * BATCH + wid * 16 + bhf[i] * 8);
                CP_COMMIT();
            }
            uint32_t stBase = myStage0 + (c & (NSTG - 1)) * SLICE_STRIDE;
            uint32_t kByte = (uint32_t)c * 128;
            #pragma unroll
            for (int ks = 0; ks < 4; ++ks) {
                uint32_t b0, b1, b2, b3;
                ldm_x4_t(b0, b1, b2, b3, stBase + bOff + ks * (16 * SLICE_PITCH));
                #pragma unroll
                for (int mt = 0; mt < 2; ++mt) {
                    uint32_t a0, a1, a2, a3;
                    ldm_x4(a0, a1, a2, a3, aOff[mt] + kByte + ks * 32);
                    mma16816(acc[mt][0], a0, a1, a2, a3, b0, b1);
                    mma16816(acc[mt][1], a0, a1, a2, a3, b2, b3);
                }
            }
        }

        // ---- LSTM cell in-register; coalesced [d][b] half2 stores ----
        {
            int d = ct * 8 + jd;
            bool last = (s == SEQ - 1);
            #pragma unroll
            for (int n = 0; n < 2; ++n) {
                int col = wid * 16 + n * 8 + 2 * tc;
                float2 pi = *(const float2*)&Psm[(0 * 8 + jd) * 128 + col];
                float2 pf = *(const float2*)&Psm[(1 * 8 + jd) * 128 + col];
                float2 pg = *(const float2*)&Psm[(2 * 8 + jd) * 128 + col];
                float2 po = *(const float2*)&Psm[(3 * 8 + jd) * 128 + col];
                float hv[2];
                #pragma unroll
                for (int e = 0; e < 2; ++e) {
                    float zi = acc[0][n][e]     + (e ? pi.y : pi.x);
                    float zf = acc[0][n][2 + e] + (e ? pf.y : pf.x);
                    float zg = acc[1][n][e]     + (e ? pg.y : pg.x);
                    float zo = acc[1][n][2 + e] + (e ? po.y : po.x);
                    float iv = sigf(zi), fv = sigf(zf), gv = tanhf(zg), ov = sigf(zo);
                    creg[n][e] = fv * creg[n][e] + iv * gv;
                    hv[e] = ov * tanhf(creg[n][e]);
                }
                __half2 hp; hp.x = __float2half(hv[0]); hp.y = __float2half(hv[1]);
                *(__half2*)&h_out[(size_t)d * BATCH + col] = hp;
                if (last) {
                    g_hfin[(size_t)col * HID + d]       = hv[0];
                    g_hfin[(size_t)(col + 1) * HID + d] = hv[1];
                }
            }
        }

        // ---- arrive / overlap P prefetch / wait ----
        __threadfence();
        __syncthreads();
        unsigned target = (unsigned)(s + 1);
        if (tid == 0) {
            unsigned old = atomicAdd(&g_bar, 1u);
            if (old == 128u * target - 1u) g_flag = target;
        }
        if (s + 1 < SEQ) {
            const float* Pg = g_P + (size_t)(s + 1) * PSTEP;
            #pragma unroll
            for (int i = 0; i < 4; ++i) {
                int qg = (pq[i] >> 3) * HID + ct * 8 + (pq[i] & 7);
                cp16(sb + SM_P + pq[i] * 512 + ps[i] * 16, Pg + (size_t)qg * BATCH + ps[i] * 4);
            }
            CP_COMMIT();
        }
        if (tid == 0) {
            while (g_flag < target) { }
            __threadfence();
        }
        __syncthreads();
    }
}

// ---------------- classifier ----------------
__global__ void out_kernel(const float* __restrict__ W_out,
                           const float* __restrict__ b_out,
                           float* __restrict__ out) {
    int c = blockIdx.x, b = blockIdx.y;
    const float* h = g_hfin + (size_t)b * HID;
    float sum = 0.0f;
    for (int d = threadIdx.x; d < HID; d += 128)
        sum += h[d] * W_out[c * HID + d];
    #pragma unroll
    for (int o = 16; o; o >>= 1) sum += __shfl_xor_sync(0xFFFFFFFFu, sum, o);
    __shared__ float red[4];
    if ((threadIdx.x & 31) == 0) red[threadIdx.x >> 5] = sum;
    __syncthreads();
    if (threadIdx.x == 0)
        out[b * NCLS + c] = red[0] + red[1] + red[2] + red[3] + b_out[c];
}

extern "C" void kernel_launch(void* const* d_in, const int* in_sizes, int n_in,
                              void* d_out, int out_size) {
    const float* x     = (const float*)d_in[0];
    const float* h0    = (const float*)d_in[1];
    const float* c0    = (const float*)d_in[2];
    const float* W_ih  = (const float*)d_in[3];
    const float* W_hh  = (const float*)d_in[4];
    const float* b_ih  = (const float*)d_in[5];
    const float* b_hh  = (const float*)d_in[6];
    const float* W_out = (const float*)d_in[7];
    const float* b_out = (const float*)d_in[8];
    float* out = (float*)d_out;

    cudaFuncSetAttribute(xproj_mma, cudaFuncAttributeMaxDynamicSharedMemorySize, XP_SMEM);
    cudaFuncSetAttribute(step_persist, cudaFuncAttributeMaxDynamicSharedMemorySize, STEP_SMEM);

    init_state<<<BATCH * HID / 256, 256>>>(h0);
    cvt_x<<<BATCH * SEQ * INDIM / 256, 256>>>(x);
    split_Wih<<<4096 * INDIM / 256, 256>>>(W_ih);
    xproj_mma<<<dim3(64, SEQ), 256, XP_SMEM>>>(b_ih, b_hh);
    step_persist<<<128, 256, STEP_SMEM>>>(W_hh, c0);
    out_kernel<<<dim3(NCLS, BATCH), 128>>>(W_out, b_out, out);
}

// round 14
// speedup vs baseline: 1.0227x; 1.0001x over previous
#include <cuda_runtime.h>
#include <cuda_fp16.h>
#include <cstdint>
#include <math.h>

#define BATCH 128
#define SEQ   512
#define INDIM 256
#define HID   1024
#define NCLS  10
#define PSTEP (4 * HID * BATCH)

// ---------------- device globals ----------------
__device__ float g_P[(size_t)SEQ * PSTEP];   // [s][q(4096)][b(128)]
__device__ __align__(16) __half g_xh[(size_t)BATCH * SEQ * INDIM];  // x fp16 [b][s][k]
__device__ __align__(16) __half g_Wihi[4096 * INDIM];   // W_ih hi fp16
__device__ __align__(16) __half g_Wilo[4096 * INDIM];   // W_ih lo fp16
__device__ __align__(16) __half g_h[2][HID * BATCH];    // [d][b] fp16 state (transposed!)
__device__ float g_hfin[BATCH * HID];                   // [b][d] final h
__device__ unsigned g_bar;
__device__ volatile unsigned g_flag;

__device__ __forceinline__ uint32_t smem_u32(const void* p) {
    uint32_t a;
    asm("{ .reg .u64 t; cvta.to.shared.u64 t, %1; cvt.u32.u64 %0, t; }" : "=r"(a) : "l"(p));
    return a;
}
__device__ __forceinline__ void cp16(uint32_t dst, const void* src) {
    asm volatile("cp.async.cg.shared.global [%0], [%1], 16;" :: "r"(dst), "l"(src));
}
#define CP_COMMIT() asm volatile("cp.async.commit_group;" ::: "memory")
#define CP_WAIT(n)  asm volatile("cp.async.wait_group %0;" :: "n"(n) : "memory")

__device__ __forceinline__ void ldm_x4(uint32_t &r0, uint32_t &r1, uint32_t &r2,
                                       uint32_t &r3, uint32_t addr) {
    asm volatile("ldmatrix.sync.aligned.m8n8.x4.shared.b16 {%0,%1,%2,%3}, [%4];"
        : "=r"(r0), "=r"(r1), "=r"(r2), "=r"(r3) : "r"(addr));
}
__device__ __forceinline__ void ldm_x4_t(uint32_t &r0, uint32_t &r1, uint32_t &r2,
                                         uint32_t &r3, uint32_t addr) {
    asm volatile("ldmatrix.sync.aligned.m8n8.x4.trans.shared.b16 {%0,%1,%2,%3}, [%4];"
        : "=r"(r0), "=r"(r1), "=r"(r2), "=r"(r3) : "r"(addr));
}
__device__ __forceinline__ void mma16816(float* c, uint32_t a0, uint32_t a1,
                                         uint32_t a2, uint32_t a3,
                                         uint32_t b0, uint32_t b1) {
    asm volatile(
        "mma.sync.aligned.m16n8k16.row.col.f32.f16.f16.f32 "
        "{%0,%1,%2,%3}, {%4,%5,%6,%7}, {%8,%9}, {%0,%1,%2,%3};"
        : "+f"(c[0]), "+f"(c[1]), "+f"(c[2]), "+f"(c[3])
        : "r"(a0), "r"(a1), "r"(a2), "r"(a3), "r"(b0), "r"(b1));
}
__device__ __forceinline__ float sigf(float x) { return 1.0f / (1.0f + __expf(-x)); }

// ---------------- pre-kernels ----------------
__global__ void init_state(const float* __restrict__ h0) {
    int idx = blockIdx.x * 256 + threadIdx.x;   // over [b][d]
    if (idx == 0) { g_bar = 0; g_flag = 0; }
    int b = idx >> 10, d = idx & 1023;
    g_h[0][d * BATCH + b] = __float2half(h0[idx]);
}
__global__ void cvt_x(const float* __restrict__ x) {
    size_t idx = (size_t)blockIdx.x * 256 + threadIdx.x;
    g_xh[idx] = __float2half(x[idx]);
}
__global__ void split_Wih(const float* __restrict__ W_ih) {
    int idx = blockIdx.x * 256 + threadIdx.x;
    float w = W_ih[idx];
    __half hi = __float2half(w);
    g_Wihi[idx] = hi;
    g_Wilo[idx] = __float2half(w - __half2float(hi));
}

// ---------------- xproj via mma.sync (fp16, W split 2-pass) ----------------
#define XP_PIT_A 264
#define XP_A_SZ  (64 * XP_PIT_A * 2)
#define XP_PIT_B 72
#define XP_B_SZ  (128 * XP_PIT_B * 2)
#define XP_SM_AHI 0
#define XP_SM_ALO XP_A_SZ
#define XP_SM_BIAS (2 * XP_A_SZ)
#define XP_SM_B   (XP_SM_BIAS + 256)
#define XP_SMEM   (XP_SM_B + 3 * XP_B_SZ)

__global__ __launch_bounds__(256, 1) void xproj_mma(
        const float* __restrict__ b_ih, const float* __restrict__ b_hh) {
    extern __shared__ char smem[];
    uint32_t sb = smem_u32(smem);
    int tid = threadIdx.x, lane = tid & 31, wid = tid >> 5;
    int li = lane >> 3, l7 = lane & 7;
    int qt = blockIdx.x, s = blockIdx.y;
    int qh = wid >> 2, bq = wid & 3;
    int q0 = qh * 32, b0 = bq * 32;

    float* bias = (float*)(smem + XP_SM_BIAS);
    if (tid < 64) {
        int q = qt * 64 + tid;
        bias[tid] = b_ih[q] + b_hh[q];
    }

    {
        #pragma unroll
        for (int i = 0; i < 8; ++i) {
            int idx = tid + i * 256;
            int row = idx >> 5, seg = idx & 31;
            cp16(sb + XP_SM_AHI + row * (XP_PIT_A * 2) + seg * 16,
                 g_Wihi + (size_t)(qt * 64 + row) * INDIM + seg * 8);
        }
        #pragma unroll
        for (int i = 0; i < 8; ++i) {
            int idx = tid + i * 256;
            int row = idx >> 5, seg = idx & 31;
            cp16(sb + XP_SM_ALO + row * (XP_PIT_A * 2) + seg * 16,
                 g_Wilo + (size_t)(qt * 64 + row) * INDIM + seg * 8);
        }
    }
    int brow[4], bseg[4];
    #pragma unroll
    for (int i = 0; i < 4; ++i) { int u = tid + i * 256; brow[i] = u >> 3; bseg[i] = u & 7; }

    auto issueB = [&](int c, int st) {
        uint32_t dst = sb + XP_SM_B + st * XP_B_SZ;
        #pragma unroll
        for (int i = 0; i < 4; ++i)
            cp16(dst + brow[i] * (XP_PIT_B * 2) + bseg[i] * 16,
                 g_xh + (size_t)brow[i] * (SEQ * INDIM) + (size_t)s * INDIM + c * 64 + bseg[i] * 8);
        CP_COMMIT();
    };
    issueB(0, 0);
    issueB(1, 1);

    uint32_t aOff[2];
    #pragma unroll
    for (int mt = 0; mt < 2; ++mt) {
        int row = q0 + mt * 16 + (li & 1) * 8 + l7;
        aOff[mt] = sb + XP_SM_AHI + (uint32_t)row * (XP_PIT_A * 2) + (li >> 1) * 16;
    }
    uint32_t bOff[2];
    #pragma unroll
    for (int p = 0; p < 2; ++p) {
        int row = b0 + p * 16 + (li >> 1) * 8 + l7;
        bOff[p] = (uint32_t)row * (XP_PIT_B * 2) + (li & 1) * 16;
    }

    float acc[2][4][4];
    #pragma unroll
    for (int mt = 0; mt < 2; ++mt)
        #pragma unroll
        for (int n = 0; n < 4; ++n)
            #pragma unroll
            for (int e = 0; e < 4; ++e) acc[mt][n][e] = 0.0f;

    #pragma unroll 1
    for (int c = 0; c < 4; ++c) {
        if (c == 3) { CP_WAIT(0); } else { CP_WAIT(1); }
        __syncthreads();
        if (c + 2 < 4) issueB(c + 2, (c + 2) % 3);
        uint32_t stBase = sb + XP_SM_B + (c % 3) * XP_B_SZ;
        uint32_t kByte = (uint32_t)c * 128;
        #pragma unroll
        for (int ks = 0; ks < 4; ++ks) {
            uint32_t bfr[4][2];
            #pragma unroll
            for (int p = 0; p < 2; ++p)
                ldm_x4(bfr[2*p][0], bfr[2*p][1], bfr[2*p+1][0], bfr[2*p+1][1],
                       stBase + bOff[p] + ks * 32);
            #pragma unroll
            for (int mt = 0; mt < 2; ++mt) {
                uint32_t a0, a1, a2, a3;
                ldm_x4(a0, a1, a2, a3, aOff[mt] + kByte + ks * 32);
                #pragma unroll
                for (int n = 0; n < 4; ++n)
                    mma16816(acc[mt][n], a0, a1, a2, a3, bfr[n][0], bfr[n][1]);
            }
            #pragma unroll
            for (int mt = 0; mt < 2; ++mt) {
                uint32_t a0, a1, a2, a3;
                ldm_x4(a0, a1, a2, a3, aOff[mt] + (uint32_t)XP_A_SZ + kByte + ks * 32);
                #pragma unroll
                for (int n = 0; n < 4; ++n)
                    mma16816(acc[mt][n], a0, a1, a2, a3, bfr[n][0], bfr[n][1]);
            }
        }
        __syncthreads();
    }

    size_t sbase = (size_t)s * PSTEP;
    #pragma unroll
    for (int mt = 0; mt < 2; ++mt) {
        #pragma unroll
        for (int n = 0; n < 4; ++n) {
            int rl0 = q0 + mt * 16 + (lane >> 2);
            int col = b0 + n * 8 + (lane & 3) * 2;
            int q0g = qt * 64 + rl0;
            float bv0 = bias[rl0], bv1 = bias[rl0 + 8];
            *(float2*)&g_P[sbase + (size_t)q0g * BATCH + col] =
                make_float2(acc[mt][n][0] + bv0, acc[mt][n][1] + bv0);
            *(float2*)&g_P[sbase + (size_t)(q0g + 8) * BATCH + col] =
                make_float2(acc[mt][n][2] + bv1, acc[mt][n][3] + bv1);
        }
    }
}

// ---------------- persistent LSTM recurrence, fp16 single-pass, [d][b] state ----------------
#define PIT_A 1032
#define SM_A  0
#define SM_P  66048
#define SM_B  82432
#define SLICE_PITCH 48           /* bytes per k-row: 16 batches fp16 (32B) + 16 pad */
#define SLICE_STRIDE 3072        /* 64 k-rows x 48 B */
#define NSTG 4
#define STEP_SMEM (SM_B + 8 * NSTG * SLICE_STRIDE)   /* 180736 */

__global__ __launch_bounds__(256, 1) void step_persist(
        const float* __restrict__ W_hh, const float* __restrict__ c0) {
    extern __shared__ char smem[];
    uint32_t sb = smem_u32(smem);
    int tid = threadIdx.x, lane = tid & 31, wid = tid >> 5;
    int li = lane >> 3, l7 = lane & 7;
    int jd = lane >> 2, tc = lane & 3;
    int ct = blockIdx.x;

    __half* sA = (__half*)(smem + SM_A);   // [32][1032]
    float* Psm = (float*)(smem + SM_P);    // [32][128]

    // ---- load A once (fp16 single) ----
    {
        int lr = tid >> 3, seg = tid & 7;
        int gate = lr >> 3, jj = lr & 7;
        const float* src = W_hh + (size_t)(gate * HID + ct * 8 + jj) * HID + seg * 128;
        #pragma unroll 4
        for (int i = 0; i < 32; ++i) {
            float4 v = *(const float4*)(src + i * 4);
            int k = seg * 128 + i * 4;
            sA[lr * PIT_A + k + 0] = __float2half(v.x);
            sA[lr * PIT_A + k + 1] = __float2half(v.y);
            sA[lr * PIT_A + k + 2] = __float2half(v.z);
            sA[lr * PIT_A + k + 3] = __float2half(v.w);
        }
    }

    // ---- c-state in registers ----
    float creg[2][2];
    {
        int d = ct * 8 + jd;
        #pragma unroll
        for (int n = 0; n < 2; ++n)
            #pragma unroll
            for (int e = 0; e < 2; ++e)
                creg[n][e] = c0[(size_t)(wid * 16 + n * 8 + 2 * tc + e) * HID + d];
    }

    uint32_t aOff[2];
    #pragma unroll
    for (int mt = 0; mt < 2; ++mt) {
        int row = mt * 16 + (li & 1) * 8 + l7;
        aOff[mt] = sb + SM_A + (uint32_t)row * (PIT_A * 2) + (li >> 1) * 16;
    }
    // B (trans): tile li: k-rows (li&1)*8 + l7, batch-halves (li>>1)*16 bytes
    uint32_t bOff = (uint32_t)((li & 1) * 8 + l7) * SLICE_PITCH + (li >> 1) * 16;
    // B cp coords: 4 units/thread, unit u = lane + i*32: k-row = u>>1, half = u&1
    int bkr[4], bhf[4];
    #pragma unroll
    for (int i = 0; i < 4; ++i) { int u = lane + i * 32; bkr[i] = u >> 1; bhf[i] = u & 1; }
    int pq[4], ps[4];
    #pragma unroll
    for (int i = 0; i < 4; ++i) { int u = tid + i * 256; pq[i] = u >> 5; ps[i] = u & 31; }

    uint32_t myStage0 = sb + SM_B + (uint32_t)wid * NSTG * SLICE_STRIDE;

    __syncthreads();

    // prefetch P(0)
    {
        #pragma unroll
        for (int i = 0; i < 4; ++i) {
            int qg = (pq[i] >> 3) * HID + ct * 8 + (pq[i] & 7);
            cp16(sb + SM_P + pq[i] * 512 + ps[i] * 16, g_P + (size_t)qg * BATCH + ps[i] * 4);
        }
        CP_COMMIT();
    }

    #pragma unroll 1
    for (int s = 0; s < SEQ; ++s) {
        const __half* h_in = g_h[s & 1];        // [d][b]
        __half* h_out = g_h[(s + 1) & 1];

        // issue B chunks 0..2
        #pragma unroll
        for (int cc = 0; cc < 3; ++cc) {
            uint32_t dst = myStage0 + cc * SLICE_STRIDE;
            #pragma unroll
            for (int i = 0; i < 4; ++i)
                cp16(dst + bkr[i] * SLICE_PITCH + bhf[i] * 16,
                     h_in + (size_t)(cc * 64 + bkr[i]) * BATCH + wid * 16 + bhf[i] * 8);
            CP_COMMIT();
        }

        float acc[2][2][4];
        #pragma unroll
        for (int mt = 0; mt < 2; ++mt)
            #pragma unroll
            for (int n = 0; n < 2; ++n)
                #pragma unroll
                for (int e = 0; e < 4; ++e) acc[mt][n][e] = 0.0f;

        #pragma unroll 1
        for (int c = 0; c < 16; ++c) {
            if (c <= 13) { CP_WAIT(2); } else if (c == 14) { CP_WAIT(1); } else { CP_WAIT(0); }
            __syncwarp();
            if (c + 3 < 16) {
                int cn = c + 3;
                uint32_t dst = myStage0 + (cn & (NSTG - 1)) * SLICE_STRIDE;
                #pragma unroll
                for (int i = 0; i < 4; ++i)
                    cp16(dst + bkr[i] * SLICE_PITCH + bhf[i] * 16,
                         h_in + (size_t)(cn * 64 + bkr[i]) * BATCH + wid * 16 + bhf[i] * 8);
                CP_COMMIT();
            }
            uint32_t stBase = myStage0 + (c & (NSTG - 1)) * SLICE_STRIDE;
            uint32_t kByte = (uint32_t)c * 128;
            #pragma unroll
            for (int ks = 0; ks < 4; ++ks) {
                uint32_t b0, b1, b2, b3;
                ldm_x4_t(b0, b1, b2, b3, stBase + bOff + ks * (16 * SLICE_PITCH));
                #pragma unroll
                for (int mt = 0; mt < 2; ++mt) {
                    uint32_t a0, a1, a2, a3;
                    ldm_x4(a0, a1, a2, a3, aOff[mt] + kByte + ks * 32);
                    mma16816(acc[mt][0], a0, a1, a2, a3, b0, b1);
                    mma16816(acc[mt][1], a0, a1, a2, a3, b2, b3);
                }
            }
        }

        // ---- LSTM cell in-register; coalesced [d][b] half2 stores ----
        {
            int d = ct * 8 + jd;
            bool last = (s == SEQ - 1);
            #pragma unroll
            for (int n = 0; n < 2; ++n) {
                int col = wid * 16 + n * 8 + 2 * tc;
                float2 pi = *(const float2*)&Psm[(0 * 8 + jd) * 128 + col];
                float2 pf = *(const float2*)&Psm[(1 * 8 + jd) * 128 + col];
                float2 pg = *(const float2*)&Psm[(2 * 8 + jd) * 128 + col];
                float2 po = *(const float2*)&Psm[(3 * 8 + jd) * 128 + col];
                float hv[2];
                #pragma unroll
                for (int e = 0; e < 2; ++e) {
                    float zi = acc[0][n][e]     + (e ? pi.y : pi.x);
                    float zf = acc[0][n][2 + e] + (e ? pf.y : pf.x);
                    float zg = acc[1][n][e]     + (e ? pg.y : pg.x);
                    float zo = acc[1][n][2 + e] + (e ? po.y : po.x);
                    float iv = sigf(zi), fv = sigf(zf), gv = tanhf(zg), ov = sigf(zo);
                    creg[n][e] = fv * creg[n][e] + iv * gv;
                    hv[e] = ov * tanhf(creg[n][e]);
                }
                __half2 hp; hp.x = __float2half(hv[0]); hp.y = __float2half(hv[1]);
                *(__half2*)&h_out[(size_t)d * BATCH + col] = hp;
                if (last) {
                    g_hfin[(size_t)col * HID + d]       = hv[0];
                    g_hfin[(size_t)(col + 1) * HID + d] = hv[1];
                }
            }
        }

        // ---- arrive / overlap P prefetch / wait ----
        __threadfence();
        __syncthreads();
        unsigned target = (unsigned)(s + 1);
        if (tid == 0) {
            unsigned old = atomicAdd(&g_bar, 1u);
            if (old == 128u * target - 1u) g_flag = target;
        }
        if (s + 1 < SEQ) {
            const float* Pg = g_P + (size_t)(s + 1) * PSTEP;
            #pragma unroll
            for (int i = 0; i < 4; ++i) {
                int qg = (pq[i] >> 3) * HID + ct * 8 + (pq[i] & 7);
                cp16(sb + SM_P + pq[i] * 512 + ps[i] * 16, Pg + (size_t)qg * BATCH + ps[i] * 4);
            }
            CP_COMMIT();
        }
        if (tid == 0) {
            while (g_flag < target) { }
            __threadfence();
        }
        __syncthreads();
    }
}

// ---------------- classifier ----------------
__global__ void out_kernel(const float* __restrict__ W_out,
                           const float* __restrict__ b_out,
                           float* __restrict__ out) {
    int c = blockIdx.x, b = blockIdx.y;
    const float* h = g_hfin + (size_t)b * HID;
    float sum = 0.0f;
    for (int d = threadIdx.x; d < HID; d += 128)
        sum += h[d] * W_out[c * HID + d];
    #pragma unroll
    for (int o = 16; o; o >>= 1) sum += __shfl_xor_sync(0xFFFFFFFFu, sum, o);
    __shared__ float red[4];
    if ((threadIdx.x & 31) == 0) red[threadIdx.x >> 5] = sum;
    __syncthreads();
    if (threadIdx.x == 0)
        out[b * NCLS + c] = red[0] + red[1] + red[2] + red[3] + b_out[c];
}

extern "C" void kernel_launch(void* const* d_in, const int* in_sizes, int n_in,
                              void* d_out, int out_size) {
    const float* x     = (const float*)d_in[0];
    const float* h0    = (const float*)d_in[1];
    const float* c0    = (const float*)d_in[2];
    const float* W_ih  = (const float*)d_in[3];
    const float* W_hh  = (const float*)d_in[4];
    const float* b_ih  = (const float*)d_in[5];
    const float* b_hh  = (const float*)d_in[6];
    const float* W_out = (const float*)d_in[7];
    const float* b_out = (const float*)d_in[8];
    float* out = (float*)d_out;

    cudaFuncSetAttribute(xproj_mma, cudaFuncAttributeMaxDynamicSharedMemorySize, XP_SMEM);
    cudaFuncSetAttribute(step_persist, cudaFuncAttributeMaxDynamicSharedMemorySize, STEP_SMEM);

    init_state<<<BATCH * HID / 256, 256>>>(h0);
    cvt_x<<<BATCH * SEQ * INDIM / 256, 256>>>(x);
    split_Wih<<<4096 * INDIM / 256, 256>>>(W_ih);
    xproj_mma<<<dim3(64, SEQ), 256, XP_SMEM>>>(b_ih, b_hh);
    step_persist<<<128, 256, STEP_SMEM>>>(W_hh, c0);
    out_kernel<<<dim3(NCLS, BATCH), 128>>>(W_out, b_out, out);
}